// round 4
// baseline (speedup 1.0000x reference)
#include <cuda_runtime.h>
#include <math.h>

#define B_ 2
#define T_ 2048
#define D_ 512
#define K_ 64
#define TT 32        // t-tile per block
#define WW 95        // window width actually used (TT + K - 1)
#define WP 100       // padded sq row stride (16B-aligned, LDS.128 conflict-free)
#define MP 96        // E row stride

// 8MB scratch for q = gelu(conv1d(x)) in [b][d][t] layout
__device__ float g_q[B_ * D_ * T_];

// ---------------------------------------------------------------------------
// Kernel A: q[b,d,t] = gelu(conv1d(x)) exact erf gelu
// ---------------------------------------------------------------------------
__global__ void conv_gelu_kernel(const float* __restrict__ x,
                                 const float* __restrict__ w,
                                 const float* __restrict__ bias) {
    int t = blockIdx.x * blockDim.x + threadIdx.x;
    int d = blockIdx.y;
    int b = blockIdx.z;
    float w0 = w[d * 3 + 0], w1 = w[d * 3 + 1], w2 = w[d * 3 + 2];
    float bb = bias[d];
    const float* xb = x + b * T_;
    float xm = (t > 0)      ? xb[t - 1] : 0.f;
    float xc = xb[t];
    float xp = (t < T_ - 1) ? xb[t + 1] : 0.f;
    float v = fmaf(w0, xm, fmaf(w1, xc, w2 * xp)) + bb;
    float g = 0.5f * v * (1.f + erff(v * 0.7071067811865476f));
    g_q[(b * D_ + d) * T_ + t] = g;
}

// ---------------------------------------------------------------------------
// Kernel B: fused banded energy + softmax + context. 1024 threads/block.
// smem: sq[512][100] + E0[32][96] + E1[32][96] = 229,376 B
// ---------------------------------------------------------------------------
extern __shared__ float smem[];

__global__ void __launch_bounds__(1024, 1)
attn_kernel(const float* __restrict__ gate, float* __restrict__ out) {
    float* sq = smem;                     // [512][100]
    float* E0 = smem + D_ * WP;           // [32][96]
    float* E1 = E0 + TT * MP;             // [32][96]

    const int tid = threadIdx.x;
    const int b   = blockIdx.y;
    const int t0  = blockIdx.x * TT;
    const float tgate = tanhf(gate[0]);

    // ---- load q window into smem (zero-fill pads) ----
    const float* qb = g_q + b * D_ * T_;
    for (int i = tid; i < D_ * WP; i += 1024) {
        int d = i / WP, w = i - d * WP;
        int wt = t0 - (K_ - 1) + w;
        float v = 0.f;
        if (w < WW && wt >= 0) v = qb[d * T_ + wt];
        sq[i] = v;
    }
    __syncthreads();

    // ---- energy: 32 x 96 rect, D split into 8 groups of 64 ----
    {
        const int qz = tid >> 7;      // D group (0..7)
        const int r  = tid & 127;
        const int tx = r & 15;        // m pair-group: m = 2*tx + 32*j (+0/1)
        const int ty = r >> 4;        // t-group: t = ty + 8*i
        float acc[4][6];
        #pragma unroll
        for (int i = 0; i < 4; i++)
            #pragma unroll
            for (int j = 0; j < 6; j++) acc[i][j] = 0.f;

        const float* sqd = sq + qz * 64 * WP;
        #pragma unroll 2
        for (int d = 0; d < 64; ++d) {
            const float* row = sqd + d * WP;
            float a[4];
            #pragma unroll
            for (int i = 0; i < 4; i++) a[i] = row[63 + ty + 8 * i];
            float2 bv[3];
            #pragma unroll
            for (int j = 0; j < 3; j++)
                bv[j] = *(const float2*)(row + 2 * tx + 32 * j);
            #pragma unroll
            for (int i = 0; i < 4; i++)
                #pragma unroll
                for (int j = 0; j < 3; j++) {
                    acc[i][2*j]   = fmaf(a[i], bv[j].x, acc[i][2*j]);
                    acc[i][2*j+1] = fmaf(a[i], bv[j].y, acc[i][2*j+1]);
                }
        }
        // accumulate 8 partials into 2 buffers in 4 phases
        float* Eo = (qz & 1) ? E1 : E0;
        const int phase = qz >> 1;
        if (phase == 0) {
            #pragma unroll
            for (int i = 0; i < 4; i++)
                #pragma unroll
                for (int j = 0; j < 3; j++)
                    *(float2*)(Eo + (ty + 8 * i) * MP + 2 * tx + 32 * j) =
                        make_float2(acc[i][2*j], acc[i][2*j+1]);
        }
        __syncthreads();
        #pragma unroll
        for (int p = 1; p < 4; ++p) {
            if (phase == p) {
                #pragma unroll
                for (int i = 0; i < 4; i++)
                    #pragma unroll
                    for (int j = 0; j < 3; j++) {
                        float2* ptr = (float2*)(Eo + (ty + 8 * i) * MP + 2 * tx + 32 * j);
                        float2 v = *ptr;
                        v.x += acc[i][2*j];
                        v.y += acc[i][2*j+1];
                        *ptr = v;
                    }
            }
            __syncthreads();
        }
    }

    // ---- softmax over k (band m in [t, t+63]); attn into E0, zero elsewhere ----
    {
        const int t = tid >> 5, lane = tid & 31;  // one warp per t row
        const float S = 0.04419417382415922f;     // 1/sqrt(512)
        float e1 = E0[t * MP + t + lane]      + E1[t * MP + t + lane];
        float e2 = E0[t * MP + t + lane + 32] + E1[t * MP + t + lane + 32];
        float mx = fmaxf(e1, e2);
        #pragma unroll
        for (int o = 16; o; o >>= 1) mx = fmaxf(mx, __shfl_xor_sync(0xffffffffu, mx, o));
        float p1 = expf((e1 - mx) * S);
        float p2 = expf((e2 - mx) * S);
        float sm = p1 + p2;
        #pragma unroll
        for (int o = 16; o; o >>= 1) sm += __shfl_xor_sync(0xffffffffu, sm, o);
        float inv = 1.f / sm;
        E0[t * MP + lane]      = 0.f;
        E0[t * MP + lane + 32] = 0.f;
        E0[t * MP + lane + 64] = 0.f;
        E0[t * MP + t + lane]      = p1 * inv;
        E0[t * MP + t + lane + 32] = p2 * inv;
    }
    __syncthreads();

    // ---- context: C[t][d] = sum_w attn[t][w] * sq[d][w]; 4t x 4d microtile ----
    {
        const int tx = tid & 127;  // d lane: d = tx + 128*j, j=0..3
        const int ty = tid >> 7;   // t group: t = 4*ty + i, i=0..3 (consecutive)
        const int w0 = 4 * ty;     // band-trimmed w start: covers [4ty, 4ty+68)
        float acc[4][4];
        #pragma unroll
        for (int i = 0; i < 4; i++)
            #pragma unroll
            for (int j = 0; j < 4; j++) acc[i][j] = 0.f;

        const float* bbase = sq + tx * WP;
        const float* abase = E0 + 4 * ty * MP;
        #pragma unroll 2
        for (int s = 0; s < 17; ++s) {
            const int w = w0 + 4 * s;
            float4 av[4], bv[4];
            #pragma unroll
            for (int i = 0; i < 4; i++)
                av[i] = *(const float4*)(abase + i * MP + w);
            #pragma unroll
            for (int j = 0; j < 4; j++)
                bv[j] = *(const float4*)(bbase + j * 128 * WP + w);
            #pragma unroll
            for (int i = 0; i < 4; i++)
                #pragma unroll
                for (int j = 0; j < 4; j++) {
                    acc[i][j] = fmaf(av[i].x, bv[j].x, acc[i][j]);
                    acc[i][j] = fmaf(av[i].y, bv[j].y, acc[i][j]);
                    acc[i][j] = fmaf(av[i].z, bv[j].z, acc[i][j]);
                    acc[i][j] = fmaf(av[i].w, bv[j].w, acc[i][j]);
                }
        }
        // direct STG.128: 4 consecutive t per thread
        #pragma unroll
        for (int j = 0; j < 4; j++) {
            float* op = out + (size_t)(b * D_ + tx + 128 * j) * T_ + t0 + 4 * ty;
            *(float4*)op = make_float4(acc[0][j] * tgate, acc[1][j] * tgate,
                                       acc[2][j] * tgate, acc[3][j] * tgate);
        }
    }
}

// ---------------------------------------------------------------------------
extern "C" void kernel_launch(void* const* d_in, const int* in_sizes, int n_in,
                              void* d_out, int out_size) {
    const float* x      = (const float*)d_in[0];  // (2,1,2048)
    const float* conv_w = (const float*)d_in[1];  // (512,1,3)
    const float* conv_b = (const float*)d_in[2];  // (512,)
    const float* gate   = (const float*)d_in[3];  // scalar
    float* out = (float*)d_out;                   // (2,512,2048)

    (void)in_sizes; (void)n_in; (void)out_size;

    dim3 gA(T_ / 256, D_, B_);
    conv_gelu_kernel<<<gA, 256>>>(x, conv_w, conv_b);

    const int smem_bytes = (D_ * WP + 2 * TT * MP) * (int)sizeof(float); // 229,376
    cudaFuncSetAttribute(attn_kernel, cudaFuncAttributeMaxDynamicSharedMemorySize, smem_bytes);
    dim3 gB(T_ / TT, B_);
    attn_kernel<<<gB, 1024, smem_bytes>>>(gate, out);
}

// round 5
// speedup vs baseline: 1.0576x; 1.0576x over previous
#include <cuda_runtime.h>
#include <math.h>

#define B_ 2
#define T_ 2048
#define D_ 512
#define K_ 64
#define TT 32        // t-tile per block
#define WW 95        // window width actually used (TT + K - 1)
#define WP 100       // padded sq row stride (16B-aligned, LDS.128 conflict-free)
#define MP 96        // E row stride

typedef unsigned long long u64;

// packed dual-fp32 ops (sm_10x f32x2 pipe; PTX-only, ptxas won't auto-fuse)
#define FMA2(d, a, b, c) \
    asm("fma.rn.f32x2 %0, %1, %2, %3;" : "=l"(d) : "l"(a), "l"(b), "l"(c))
#define ADD2(d, a, b) \
    asm("add.rn.f32x2 %0, %1, %2;" : "=l"(d) : "l"(a), "l"(b))
#define PACKDUP(d, x) \
    asm("mov.b64 %0, {%1, %1};" : "=l"(d) : "f"(x))

// 8MB scratch for q = gelu(conv1d(x)) in [b][d][t] layout
__device__ float g_q[B_ * D_ * T_];

// ---------------------------------------------------------------------------
// Kernel A: q[b,d,t] = gelu(conv1d(x)) exact erf gelu
// ---------------------------------------------------------------------------
__global__ void conv_gelu_kernel(const float* __restrict__ x,
                                 const float* __restrict__ w,
                                 const float* __restrict__ bias) {
    int t = blockIdx.x * blockDim.x + threadIdx.x;
    int d = blockIdx.y;
    int b = blockIdx.z;
    float w0 = w[d * 3 + 0], w1 = w[d * 3 + 1], w2 = w[d * 3 + 2];
    float bb = bias[d];
    const float* xb = x + b * T_;
    float xm = (t > 0)      ? xb[t - 1] : 0.f;
    float xc = xb[t];
    float xp = (t < T_ - 1) ? xb[t + 1] : 0.f;
    float v = fmaf(w0, xm, fmaf(w1, xc, w2 * xp)) + bb;
    float g = 0.5f * v * (1.f + erff(v * 0.7071067811865476f));
    g_q[(b * D_ + d) * T_ + t] = g;
}

// ---------------------------------------------------------------------------
// Kernel B: fused banded energy + softmax + context. 1024 threads/block.
// smem: sq[512][100] + E0[32][96] + E1[32][96] = 229,376 B
// ---------------------------------------------------------------------------
extern __shared__ float smem[];

__global__ void __launch_bounds__(1024, 1)
attn_kernel(const float* __restrict__ gate, float* __restrict__ out) {
    float* sq = smem;                     // [512][100]
    float* E0 = smem + D_ * WP;           // [32][96]
    float* E1 = E0 + TT * MP;             // [32][96]

    const int tid = threadIdx.x;
    const int b   = blockIdx.y;
    const int t0  = blockIdx.x * TT;
    const float tgate = tanhf(gate[0]);

    // ---- load q window into smem (zero-fill pads) ----
    const float* qb = g_q + b * D_ * T_;
    for (int i = tid; i < D_ * WP; i += 1024) {
        int d = i / WP, w = i - d * WP;
        int wt = t0 - (K_ - 1) + w;
        float v = 0.f;
        if (w < WW && wt >= 0) v = qb[d * T_ + wt];
        sq[i] = v;
    }
    __syncthreads();

    // ---- energy: 32 x 96 rect, D split into 8 groups of 64, f32x2 FMA ----
    {
        const int qz = tid >> 7;      // D group (0..7)
        const int r  = tid & 127;
        const int tx = r & 15;        // m pair-group: m = 2*tx + 32*j (+0/1)
        const int ty = r >> 4;        // t-group: t = ty + 8*i
        u64 acc2[4][3];
        #pragma unroll
        for (int i = 0; i < 4; i++)
            #pragma unroll
            for (int j = 0; j < 3; j++) acc2[i][j] = 0ull;

        const float* sqd = sq + qz * 64 * WP;
        #pragma unroll 2
        for (int d = 0; d < 64; ++d) {
            const float* row = sqd + d * WP;
            u64 a2[4];
            #pragma unroll
            for (int i = 0; i < 4; i++) {
                float av = row[63 + ty + 8 * i];
                PACKDUP(a2[i], av);
            }
            u64 bv2[3];
            #pragma unroll
            for (int j = 0; j < 3; j++)
                bv2[j] = *(const u64*)(row + 2 * tx + 32 * j);
            #pragma unroll
            for (int i = 0; i < 4; i++)
                #pragma unroll
                for (int j = 0; j < 3; j++)
                    FMA2(acc2[i][j], a2[i], bv2[j], acc2[i][j]);
        }
        // accumulate 8 partials into 2 buffers in 4 phases (packed adds)
        float* Eo = (qz & 1) ? E1 : E0;
        const int phase = qz >> 1;
        if (phase == 0) {
            #pragma unroll
            for (int i = 0; i < 4; i++)
                #pragma unroll
                for (int j = 0; j < 3; j++)
                    *(u64*)(Eo + (ty + 8 * i) * MP + 2 * tx + 32 * j) = acc2[i][j];
        }
        __syncthreads();
        #pragma unroll
        for (int p = 1; p < 4; ++p) {
            if (phase == p) {
                #pragma unroll
                for (int i = 0; i < 4; i++)
                    #pragma unroll
                    for (int j = 0; j < 3; j++) {
                        u64* ptr = (u64*)(Eo + (ty + 8 * i) * MP + 2 * tx + 32 * j);
                        u64 v = *ptr;
                        ADD2(v, v, acc2[i][j]);
                        *ptr = v;
                    }
            }
            __syncthreads();
        }
    }

    // ---- softmax over k (band m in [t, t+63]); attn into E0, zero elsewhere ----
    {
        const int t = tid >> 5, lane = tid & 31;  // one warp per t row
        const float S = 0.04419417382415922f;     // 1/sqrt(512)
        float e1 = E0[t * MP + t + lane]      + E1[t * MP + t + lane];
        float e2 = E0[t * MP + t + lane + 32] + E1[t * MP + t + lane + 32];
        float mx = fmaxf(e1, e2);
        #pragma unroll
        for (int o = 16; o; o >>= 1) mx = fmaxf(mx, __shfl_xor_sync(0xffffffffu, mx, o));
        float p1 = expf((e1 - mx) * S);
        float p2 = expf((e2 - mx) * S);
        float sm = p1 + p2;
        #pragma unroll
        for (int o = 16; o; o >>= 1) sm += __shfl_xor_sync(0xffffffffu, sm, o);
        float inv = 1.f / sm;
        E0[t * MP + lane]      = 0.f;
        E0[t * MP + lane + 32] = 0.f;
        E0[t * MP + lane + 64] = 0.f;
        E0[t * MP + t + lane]      = p1 * inv;
        E0[t * MP + t + lane + 32] = p2 * inv;
    }
    __syncthreads();

    // ---- context: C[t][d] = sum_w attn[t][w] * sq[d][w]; 4t x 4d, f32x2 ----
    {
        const int tx = tid & 127;  // d lane: d = tx + 128*j, j=0..3
        const int ty = tid >> 7;   // t group: t = 4*ty + i, i=0..3 (consecutive)
        const int w0 = 4 * ty;     // band-trimmed w start: covers [4ty, 4ty+68)
        u64 acc2[4][4];
        #pragma unroll
        for (int i = 0; i < 4; i++)
            #pragma unroll
            for (int j = 0; j < 4; j++) acc2[i][j] = 0ull;

        const float* bbase = sq + tx * WP;
        const float* abase = E0 + 4 * ty * MP;
        #pragma unroll 2
        for (int s = 0; s < 17; ++s) {
            const int w = w0 + 4 * s;
            u64 avl[4], avh[4];
            #pragma unroll
            for (int i = 0; i < 4; i++) {
                const float* ap = abase + i * MP + w;
                avl[i] = *(const u64*)(ap);
                avh[i] = *(const u64*)(ap + 2);
            }
            #pragma unroll
            for (int j = 0; j < 4; j++) {
                const float* bp = bbase + j * 128 * WP + w;
                u64 bvl = *(const u64*)(bp);
                u64 bvh = *(const u64*)(bp + 2);
                #pragma unroll
                for (int i = 0; i < 4; i++) {
                    FMA2(acc2[i][j], avl[i], bvl, acc2[i][j]);
                    FMA2(acc2[i][j], avh[i], bvh, acc2[i][j]);
                }
            }
        }
        // horizontal add + direct STG.128: 4 consecutive t per thread
        #pragma unroll
        for (int j = 0; j < 4; j++) {
            float c[4];
            #pragma unroll
            for (int i = 0; i < 4; i++) {
                float2 p = *(float2*)&acc2[i][j];
                c[i] = (p.x + p.y) * tgate;
            }
            float* op = out + (size_t)(b * D_ + tx + 128 * j) * T_ + t0 + 4 * ty;
            *(float4*)op = make_float4(c[0], c[1], c[2], c[3]);
        }
    }
}

// ---------------------------------------------------------------------------
extern "C" void kernel_launch(void* const* d_in, const int* in_sizes, int n_in,
                              void* d_out, int out_size) {
    const float* x      = (const float*)d_in[0];  // (2,1,2048)
    const float* conv_w = (const float*)d_in[1];  // (512,1,3)
    const float* conv_b = (const float*)d_in[2];  // (512,)
    const float* gate   = (const float*)d_in[3];  // scalar
    float* out = (float*)d_out;                   // (2,512,2048)

    (void)in_sizes; (void)n_in; (void)out_size;

    dim3 gA(T_ / 256, D_, B_);
    conv_gelu_kernel<<<gA, 256>>>(x, conv_w, conv_b);

    const int smem_bytes = (D_ * WP + 2 * TT * MP) * (int)sizeof(float); // 229,376
    cudaFuncSetAttribute(attn_kernel, cudaFuncAttributeMaxDynamicSharedMemorySize, smem_bytes);
    dim3 gB(T_ / TT, B_);
    attn_kernel<<<gB, 1024, smem_bytes>>>(gate, out);
}